// round 11
// baseline (speedup 1.0000x reference)
#include <cuda_runtime.h>
#include <cuda_fp16.h>
#include <cstdint>
#include <math.h>

static constexpr int B_ = 8, S_ = 2048, D_ = 1024, H_ = 1024;
static constexpr int M_ = B_ * S_;  // 16384

// Tiling: 128x256 CTA tile, BK=32, warp tile 64x64 (2x4 warps).
static constexpr int BM = 128, BN = 256, BK = 32;
static constexpr int ROWB = 80;                    // 64 data bytes + 16 pad
static constexpr int APL = BM * ROWB;              // 10240 (A plane)
static constexpr int BPL = BN * ROWB;              // 20480 (B plane)
static constexpr int STG = APL + BPL;              // 30720 per stage
static constexpr int NST = 4;
static constexpr int SMEM_BYTES = NST * STG;       // 122880

static constexpr float SHIFT = 3.0f;               // exp(s - SHIFT), cancels in norm
static constexpr float LOG2E = 1.4426950408889634f;

// Device scratch (allocation-free rule: __device__ globals)
__device__ __half g_xh[(size_t)M_ * D_];
__device__ __half g_wh[3][(size_t)H_ * D_];
__device__ __half g_qkv[3][(size_t)M_ * H_];       // q, k, v planes
__device__ __half g_vth[(size_t)M_ * H_];
__device__ __half g_ph[(size_t)B_ * S_ * S_];
__device__ float  g_rinv[M_];

// ---------------------------------------------------------------------------
// helpers
// ---------------------------------------------------------------------------
__device__ __forceinline__ uint32_t smem_u32(const void* p) {
    uint32_t a;
    asm("{ .reg .u64 t; cvta.to.shared.u64 t, %1; cvt.u32.u64 %0, t; }"
        : "=r"(a) : "l"(p));
    return a;
}

#define CP16(dst, src) \
    asm volatile("cp.async.cg.shared.global [%0], [%1], 16;" :: "r"(dst), "l"(src))
#define CP_COMMIT() asm volatile("cp.async.commit_group;" ::: "memory")
#define CP_WAIT2()  asm volatile("cp.async.wait_group 2;" ::: "memory")

__device__ __forceinline__ void mma16(float* d, const uint32_t* a, const uint32_t* b) {
    asm volatile(
        "mma.sync.aligned.m16n8k16.row.col.f32.f16.f16.f32 "
        "{%0,%1,%2,%3},{%4,%5,%6,%7},{%8,%9},{%0,%1,%2,%3};"
        : "+f"(d[0]), "+f"(d[1]), "+f"(d[2]), "+f"(d[3])
        : "r"(a[0]), "r"(a[1]), "r"(a[2]), "r"(a[3]), "r"(b[0]), "r"(b[1]));
}

__device__ __forceinline__ void ldsm4(uint32_t* r, uint32_t addr) {
    asm volatile(
        "ldmatrix.sync.aligned.m8n8.x4.shared.b16 {%0,%1,%2,%3}, [%4];"
        : "=r"(r[0]), "=r"(r[1]), "=r"(r[2]), "=r"(r[3]) : "r"(addr));
}

// triangular tile count helper: tiles for rows < mt when BN = 2*BM
__host__ __device__ __forceinline__ int tri_cum(int mt) {
    const int h = mt >> 1, odd = mt & 1;
    return h * (h + 1) + odd * (h + 1);
}

// ---------------------------------------------------------------------------
// Per-stage compute: 2 k16 steps, warp tile 64x64, single-pass fp16.
// ---------------------------------------------------------------------------
__device__ __forceinline__ void compute_tile(
    uint32_t buf, float (&acc)[4][8][4], uint32_t aBase, uint32_t bBase)
{
#pragma unroll
    for (int ks = 0; ks < 2; ks++) {
        const uint32_t kb = ks * 32;
        uint32_t bh[4][4];
#pragma unroll
        for (int ntp = 0; ntp < 4; ntp++)
            ldsm4(bh[ntp], buf + APL + bBase + ntp * 16 * ROWB + kb);
#pragma unroll
        for (int mt = 0; mt < 4; mt++) {
            uint32_t af[4];
            ldsm4(af, buf + aBase + mt * 16 * ROWB + kb);
#pragma unroll
            for (int nt = 0; nt < 8; nt++) {
                const int ntp = nt >> 1, s = nt & 1;
                uint32_t b0[2] = {bh[ntp][s], bh[ntp][s + 2]};
                mma16(acc[mt][nt], af, b0);
            }
        }
    }
}

// ---------------------------------------------------------------------------
// NT GEMM on fp16 planes: C[m,n] = sum_k A[m,k]*B[n,k]
// MODE 0: fused QKV   -> z selects W plane / bias / output plane
// MODE 2: scores      -> triangular-packed grid; fp16 exp(s*scale - SHIFT)
// MODE 3: PV          -> fp32 * rinv[row], Kend = m0+BM, largest-K-first order
// ---------------------------------------------------------------------------
template <int MODE>
__global__ __launch_bounds__(256, 1) void gemm_h(
    const __half* __restrict__ A, const __half* __restrict__ Bh,
    const float* __restrict__ bias0, const float* __restrict__ bias1,
    const float* __restrict__ bias2, void* __restrict__ C0,
    const float* __restrict__ rinv,
    int K, int lda, int ldb, int ldc,
    long sAz, long sBz, long sCz, float scale)
{
    int m0, n0;
    if (MODE == 2) {
        // packed triangular decode: t -> (mt, nt) with n0 <= m0
        const int t = blockIdx.x;
        int mt = 0;
        while (tri_cum(mt + 1) <= t) mt++;
        m0 = mt * BM;
        n0 = (t - tri_cum(mt)) * BN;
    } else if (MODE == 3) {
        m0 = ((int)gridDim.y - 1 - (int)blockIdx.y) * BM;  // largest K first
        n0 = blockIdx.x * BN;
    } else {
        m0 = blockIdx.y * BM;
        n0 = blockIdx.x * BN;
    }

    const int z = blockIdx.z;
    A  += (size_t)z * sAz;
    Bh += (size_t)z * sBz;

    extern __shared__ char smx[];
    const uint32_t smb = smem_u32(smx);

    const int tid  = threadIdx.x;
    const int lane = tid & 31;
    const int wid  = tid >> 5;
    const int wm   = wid >> 2;   // 0..1 (64 rows)
    const int wn   = wid & 3;    // 0..3 (64 cols)
    const int g    = lane >> 2;
    const int tg   = lane & 3;

    // ldmatrix lane addressing
    const uint32_t lq = lane & 15, lh = lane >> 4;
    const uint32_t aBase = (wm * 64 + lq) * ROWB + lh * 16;
    const uint32_t bBase = (wn * 64 + lq) * ROWB + lh * 16;

    const int Kend = (MODE == 3) ? (m0 + BM) : K;
    const int KT   = Kend / BK;

    // cp.async mapping: 16B segment c16 of the 64B row
    const int lr4 = tid >> 2;
    const int c16 = tid & 3;
    const __half* pA  = A  + (size_t)(m0 + lr4) * lda + c16 * 8;
    const __half* pBh = Bh + (size_t)(n0 + lr4) * ldb + c16 * 8;
    const size_t a64 = (size_t)64 * lda, b64 = (size_t)64 * ldb;
    const uint32_t dstA = smb + lr4 * ROWB + c16 * 16;
    const uint32_t dstB = smb + APL + lr4 * ROWB + c16 * 16;

    float acc[4][8][4];
#pragma unroll
    for (int i = 0; i < 4; i++)
#pragma unroll
        for (int j = 0; j < 8; j++)
#pragma unroll
            for (int e = 0; e < 4; e++) acc[i][j][e] = 0.f;

#define ISSUE(kt)                                                          \
    do {                                                                   \
        const uint32_t so = ((kt) % NST) * STG;                            \
        const int koff = (kt) * BK;                                        \
        CP16(dstA + so,              pA  + koff);                          \
        CP16(dstA + so + 64 * ROWB,  pA  + koff + a64);                    \
        CP16(dstB + so,              pBh + koff);                          \
        CP16(dstB + so + 64 * ROWB,  pBh + koff + b64);                    \
        CP16(dstB + so + 128 * ROWB, pBh + koff + 2 * b64);                \
        CP16(dstB + so + 192 * ROWB, pBh + koff + 3 * b64);                \
        CP_COMMIT();                                                       \
    } while (0)

    ISSUE(0);
    ISSUE(1);
    ISSUE(2);

    for (int kt = 0; kt < KT; kt++) {
        CP_WAIT2();          // stage kt resident (<=2 groups outstanding)
        __syncthreads();     // all warps done with the buffer being rewritten
        if (kt + 3 < KT) ISSUE(kt + 3);
        compute_tile(smb + (kt % NST) * STG, acc, aBase, bBase);
    }
#undef ISSUE

    // epilogue
#pragma unroll
    for (int mt = 0; mt < 4; mt++)
#pragma unroll
        for (int nt = 0; nt < 8; nt++) {
            const int row = m0 + wm * 64 + mt * 16 + g;
            const int col = n0 + wn * 64 + nt * 8 + tg * 2;
            float* c = acc[mt][nt];
            if (MODE == 0) {
                __half* Ch = (__half*)C0 + (size_t)z * sCz;
                const float* bias = (z == 0) ? bias0 : ((z == 1) ? bias1 : bias2);
                const float2 b2 = *(const float2*)(bias + col);
                __half2 h0 = __floats2half2_rn(c[0] + b2.x, c[1] + b2.y);
                __half2 h1 = __floats2half2_rn(c[2] + b2.x, c[3] + b2.y);
                *(__half2*)(Ch + (size_t)row * ldc + col)       = h0;
                *(__half2*)(Ch + (size_t)(row + 8) * ldc + col) = h1;
            } else if (MODE == 2) {
                __half* Ph = (__half*)C0 + (size_t)z * sCz;
                float e0 = (col     <= row    ) ? exp2f((c[0] * scale - SHIFT) * LOG2E) : 0.f;
                float e1 = (col + 1 <= row    ) ? exp2f((c[1] * scale - SHIFT) * LOG2E) : 0.f;
                float e2 = (col     <= row + 8) ? exp2f((c[2] * scale - SHIFT) * LOG2E) : 0.f;
                float e3 = (col + 1 <= row + 8) ? exp2f((c[3] * scale - SHIFT) * LOG2E) : 0.f;
                *(__half2*)(Ph + (size_t)row * ldc + col)       = __floats2half2_rn(e0, e1);
                *(__half2*)(Ph + (size_t)(row + 8) * ldc + col) = __floats2half2_rn(e2, e3);
            } else {
                float* C = (float*)C0 + (size_t)z * sCz;
                const float r0 = rinv[z * S_ + row];
                const float r1 = rinv[z * S_ + row + 8];
                *(float2*)(C + (size_t)row * ldc + col) =
                    make_float2(c[0] * r0, c[1] * r0);
                *(float2*)(C + (size_t)(row + 8) * ldc + col) =
                    make_float2(c[2] * r1, c[3] * r1);
            }
        }
}

// ---------------------------------------------------------------------------
// fp32 -> fp16 conversion (single src)
// ---------------------------------------------------------------------------
__global__ __launch_bounds__(256) void cvt_h(
    const float* __restrict__ in, __half* __restrict__ out)
{
    const size_t i = ((size_t)blockIdx.x * 256 + threadIdx.x) * 4;
    float4 v = *(const float4*)(in + i);
    *(__half2*)(out + i)     = __floats2half2_rn(v.x, v.y);
    *(__half2*)(out + i + 2) = __floats2half2_rn(v.z, v.w);
}

// fp32 -> fp16 conversion for the 3 weight matrices (z-indexed)
__global__ __launch_bounds__(256) void cvt_w(
    const float* __restrict__ w0, const float* __restrict__ w1,
    const float* __restrict__ w2, __half* __restrict__ out)
{
    const int z = blockIdx.y;
    const float* in = (z == 0) ? w0 : ((z == 1) ? w1 : w2);
    const size_t i = ((size_t)blockIdx.x * 256 + threadIdx.x) * 4;
    float4 v = *(const float4*)(in + i);
    __half* o = out + (size_t)z * H_ * D_;
    *(__half2*)(o + i)     = __floats2half2_rn(v.x, v.y);
    *(__half2*)(o + i + 2) = __floats2half2_rn(v.z, v.w);
}

// ---------------------------------------------------------------------------
// fp16 transpose: in [M_][H_] -> out [H_][M_]
// ---------------------------------------------------------------------------
__global__ __launch_bounds__(256) void transpose_h(
    const __half* __restrict__ in, __half* __restrict__ out)
{
    __shared__ __half t[32][34];
    const int x0 = blockIdx.x * 32;
    const int y0 = blockIdx.y * 32;
    const int tx = threadIdx.x & 31;
    const int ty = threadIdx.x >> 5;
#pragma unroll
    for (int j = 0; j < 32; j += 8)
        t[ty + j][tx] = in[(size_t)(y0 + ty + j) * H_ + x0 + tx];
    __syncthreads();
#pragma unroll
    for (int j = 0; j < 32; j += 8)
        out[(size_t)(x0 + ty + j) * M_ + y0 + tx] = t[tx][ty + j];
}

// ---------------------------------------------------------------------------
// Row sum of p~ over the causal prefix -> rinv = 1/sum (deterministic).
// ---------------------------------------------------------------------------
__global__ __launch_bounds__(256) void rowsum_k(
    const __half* __restrict__ Ph, float* __restrict__ rinv)
{
    const int r = blockIdx.x;
    const int m = r & (S_ - 1);
    const __half* row = Ph + (size_t)r * S_;
    const int KB = ((m >> 7) + 1) << 7;  // round_up(m+1,128)

    __shared__ float red[8];
    const int tid = threadIdx.x;

    float sm = 0.f;
    for (int i = tid * 2; i < KB; i += 512) {
        __half2 v = *(const __half2*)(row + i);
        float2 f = __half22float2(v);
        sm += f.x + f.y;
    }
#pragma unroll
    for (int o = 16; o; o >>= 1) sm += __shfl_xor_sync(0xffffffffu, sm, o);
    if ((tid & 31) == 0) red[tid >> 5] = sm;
    __syncthreads();
    if (tid == 0) {
        float t = 0.f;
#pragma unroll
        for (int i = 0; i < 8; i++) t += red[i];
        rinv[r] = 1.f / t;
    }
}

// ---------------------------------------------------------------------------
// Launch pipeline (graph-capturable)
// ---------------------------------------------------------------------------
extern "C" void kernel_launch(void* const* d_in, const int* in_sizes, int n_in,
                              void* d_out, int out_size)
{
    (void)in_sizes; (void)n_in; (void)out_size;
    const float* x  = (const float*)d_in[0];
    const float* Wq = (const float*)d_in[1];
    const float* bq = (const float*)d_in[2];
    const float* Wk = (const float*)d_in[3];
    const float* bk = (const float*)d_in[4];
    const float* Wv = (const float*)d_in[5];
    const float* bv = (const float*)d_in[6];
    float* out = (float*)d_out;

    __half *xh, *wh, *qkv, *vth, *ph;
    float* rinv;
    cudaGetSymbolAddress((void**)&xh,   g_xh);
    cudaGetSymbolAddress((void**)&wh,   g_wh);
    cudaGetSymbolAddress((void**)&qkv,  g_qkv);
    cudaGetSymbolAddress((void**)&vth,  g_vth);
    cudaGetSymbolAddress((void**)&ph,   g_ph);
    cudaGetSymbolAddress((void**)&rinv, g_rinv);

    const __half* qh = qkv;
    const __half* kh = qkv + (size_t)M_ * H_;
    const __half* vh = qkv + 2 * (size_t)M_ * H_;

    cudaFuncSetAttribute(gemm_h<0>, cudaFuncAttributeMaxDynamicSharedMemorySize, SMEM_BYTES);
    cudaFuncSetAttribute(gemm_h<2>, cudaFuncAttributeMaxDynamicSharedMemorySize, SMEM_BYTES);
    cudaFuncSetAttribute(gemm_h<3>, cudaFuncAttributeMaxDynamicSharedMemorySize, SMEM_BYTES);

    const dim3 blk(256);

    // 0) convert operands to fp16
    cvt_h<<<M_ * D_ / 1024, blk>>>(x, xh);
    cvt_w<<<dim3(H_ * D_ / 1024, 3), blk>>>(Wq, Wk, Wv, wh);

    // 1) fused QKV projection: one launch, z selects plane
    const dim3 gq(H_ / BN, M_ / BM, 3);  // (4, 128, 3) = 1536 CTAs
    gemm_h<0><<<gq, blk, SMEM_BYTES>>>(xh, wh, bq, bk, bv, qkv, nullptr,
                                       D_, D_, D_, H_,
                                       0, (long)H_ * D_, (long)M_ * H_, 1.f);

    // 1b) V^T for the PV GEMM
    transpose_h<<<dim3(H_ / 32, M_ / 32), blk>>>(vh, vth);

    // 2) Scores -> p~ = exp(s/32 - SHIFT), fp16, causal; packed triangular grid
    const dim3 gs(tri_cum(S_ / BM), 1, B_);  // (72, 1, 8)
    gemm_h<2><<<gs, blk, SMEM_BYTES>>>(qh, kh, nullptr, nullptr, nullptr, ph, nullptr,
                                       H_, H_, H_, S_,
                                       (long)S_ * H_, (long)S_ * H_, (long)S_ * S_,
                                       0.03125f);

    // 3) rinv[r] = 1 / rowsum(p~)
    rowsum_k<<<M_, blk>>>(ph, rinv);

    // 4) O = (p~ @ V) * rinv  (B = V^T, causal k-limit, largest-K tiles first)
    const dim3 gp(H_ / BN, S_ / BM, B_);  // (4, 16, 8)
    gemm_h<3><<<gp, blk, SMEM_BYTES>>>(ph, vth, nullptr, nullptr, nullptr, out, rinv,
                                       S_, S_, M_, H_,
                                       (long)S_ * S_, (long)S_, (long)S_ * H_, 1.f);
}

// round 12
// speedup vs baseline: 1.1637x; 1.1637x over previous
#include <cuda_runtime.h>
#include <cuda_fp16.h>
#include <cstdint>
#include <math.h>

static constexpr int B_ = 8, S_ = 2048, D_ = 1024, H_ = 1024;
static constexpr int M_ = B_ * S_;  // 16384

// Tiling: 128x128 CTA tile, BK=32. fp16 planes in SMEM: A_h, B_h. (R10 config)
static constexpr int BM = 128, BN = 128, BK = 32;
static constexpr int ROWB = 80;                    // 64 data bytes + 16 pad
static constexpr int PL = BM * ROWB;               // 10240 per plane
static constexpr int STG = 2 * PL;                 // 20480 per stage
static constexpr int NST = 4;
static constexpr int SMEM_BYTES = NST * STG;       // 81920

static constexpr float SHIFT = 3.0f;               // exp(s - SHIFT), cancels in norm
static constexpr float LOG2E = 1.4426950408889634f;

// Device scratch (allocation-free rule: __device__ globals)
__device__ __half g_xh[(size_t)M_ * D_];
__device__ __half g_wh[3][(size_t)H_ * D_];
__device__ __half g_qkv[2][(size_t)M_ * H_];       // q, k planes
__device__ __half g_vth[(size_t)M_ * H_];          // V transposed [H][M]
__device__ __half g_ph[(size_t)B_ * S_ * S_];
__device__ float  g_rsum[M_];

// ---------------------------------------------------------------------------
// helpers
// ---------------------------------------------------------------------------
__device__ __forceinline__ uint32_t smem_u32(const void* p) {
    uint32_t a;
    asm("{ .reg .u64 t; cvta.to.shared.u64 t, %1; cvt.u32.u64 %0, t; }"
        : "=r"(a) : "l"(p));
    return a;
}

#define CP16(dst, src) \
    asm volatile("cp.async.cg.shared.global [%0], [%1], 16;" :: "r"(dst), "l"(src))
#define CP_COMMIT() asm volatile("cp.async.commit_group;" ::: "memory")
#define CP_WAIT2()  asm volatile("cp.async.wait_group 2;" ::: "memory")
#define CP_WAIT1()  asm volatile("cp.async.wait_group 1;" ::: "memory")
#define CP_WAIT0()  asm volatile("cp.async.wait_group 0;" ::: "memory")

__device__ __forceinline__ void mma16(float* d, const uint32_t* a, const uint32_t* b) {
    asm volatile(
        "mma.sync.aligned.m16n8k16.row.col.f32.f16.f16.f32 "
        "{%0,%1,%2,%3},{%4,%5,%6,%7},{%8,%9},{%0,%1,%2,%3};"
        : "+f"(d[0]), "+f"(d[1]), "+f"(d[2]), "+f"(d[3])
        : "r"(a[0]), "r"(a[1]), "r"(a[2]), "r"(a[3]), "r"(b[0]), "r"(b[1]));
}

__device__ __forceinline__ void ldsm4(uint32_t* r, uint32_t addr) {
    asm volatile(
        "ldmatrix.sync.aligned.m8n8.x4.shared.b16 {%0,%1,%2,%3}, [%4];"
        : "=r"(r[0]), "=r"(r[1]), "=r"(r[2]), "=r"(r[3]) : "r"(addr));
}

// ---------------------------------------------------------------------------
// Per-stage compute: 2 k16 steps, warp tile 64x32, single-pass fp16.
// ---------------------------------------------------------------------------
__device__ __forceinline__ void compute_tile(
    uint32_t buf, float (&acc)[4][4][4], uint32_t aBase, uint32_t bBase)
{
#pragma unroll
    for (int ks = 0; ks < 2; ks++) {
        const uint32_t kb = ks * 32;
        uint32_t bh[2][4];
#pragma unroll
        for (int ntp = 0; ntp < 2; ntp++)
            ldsm4(bh[ntp], buf + PL + bBase + ntp * 16 * ROWB + kb);
#pragma unroll
        for (int mt = 0; mt < 4; mt++) {
            uint32_t af[4];
            ldsm4(af, buf + aBase + mt * 16 * ROWB + kb);
#pragma unroll
            for (int nt = 0; nt < 4; nt++) {
                const int ntp = nt >> 1, s = nt & 1;
                uint32_t b0[2] = {bh[ntp][s], bh[ntp][s + 2]};
                mma16(acc[mt][nt], af, b0);
            }
        }
    }
}

// ---------------------------------------------------------------------------
// NT GEMM on fp16 planes: C[m,n] = sum_k A[m,k]*B[n,k]
// MODE 0: fused QKV -> z=0/1 write q/k planes; z=2 writes V TRANSPOSED to vt
// MODE 2: scores    -> triangular grid; p~=exp(s*scale-SHIFT); atomic row sums
// MODE 3: PV        -> fp32 / rsum[row], Kend = m0+BM, largest-K-first order
// ---------------------------------------------------------------------------
template <int MODE>
__global__ __launch_bounds__(256, 2) void gemm_h(
    const __half* __restrict__ A, const __half* __restrict__ Bh,
    const float* __restrict__ bias0, const float* __restrict__ bias1,
    const float* __restrict__ bias2, void* __restrict__ C0,
    __half* __restrict__ vt_out, float* __restrict__ rsum,
    int K, int lda, int ldb, int ldc,
    long sAz, long sBz, long sCz, float scale)
{
    int m0, n0;
    if (MODE == 2) {
        // triangular decode: blockIdx.x in [0,136) -> (mt, nt), nt <= mt
        const int t = blockIdx.x;
        int mt = (int)((__fsqrt_rn(8.f * t + 1.f) - 1.f) * 0.5f);
        while ((mt + 1) * (mt + 2) / 2 <= t) mt++;
        while (mt * (mt + 1) / 2 > t) mt--;
        m0 = mt * BM;
        n0 = (t - mt * (mt + 1) / 2) * BN;
    } else if (MODE == 3) {
        m0 = ((int)gridDim.y - 1 - (int)blockIdx.y) * BM;  // largest K first
        n0 = blockIdx.x * BN;
    } else {
        m0 = blockIdx.y * BM;
        n0 = blockIdx.x * BN;
    }

    const int z = blockIdx.z;
    A  += (size_t)z * sAz;
    Bh += (size_t)z * sBz;

    extern __shared__ char smx[];
    const uint32_t smb = smem_u32(smx);

    const int tid  = threadIdx.x;
    const int lane = tid & 31;
    const int wid  = tid >> 5;
    const int wm   = wid >> 2;   // 0..1 (64 rows)
    const int wn   = wid & 3;    // 0..3 (32 cols)
    const int g    = lane >> 2;
    const int tg   = lane & 3;

    // ldmatrix lane addressing
    const uint32_t lq = lane & 15, lh = lane >> 4;
    const uint32_t aBase = (wm * 64 + lq) * ROWB + lh * 16;
    const uint32_t bBase = (wn * 32 + lq) * ROWB + lh * 16;

    const int Kend = (MODE == 3) ? (m0 + BM) : K;
    const int KT   = Kend / BK;

    // cp.async mapping: rows lr4 and lr4+64, 16B segment c16 of the 64B row
    const int lr4 = tid >> 2;
    const int c16 = tid & 3;
    const __half* pA  = A  + (size_t)(m0 + lr4) * lda + c16 * 8;
    const __half* pBh = Bh + (size_t)(n0 + lr4) * ldb + c16 * 8;
    const size_t a64 = (size_t)64 * lda, b64 = (size_t)64 * ldb;
    const uint32_t dst0 = smb + lr4 * ROWB + c16 * 16;

    float acc[4][4][4];
#pragma unroll
    for (int i = 0; i < 4; i++)
#pragma unroll
        for (int j = 0; j < 4; j++)
#pragma unroll
            for (int e = 0; e < 4; e++) acc[i][j][e] = 0.f;

#define ISSUE(kt)                                                          \
    do {                                                                   \
        const uint32_t d = dst0 + ((kt) % NST) * STG;                      \
        const int koff = (kt) * BK;                                        \
        CP16(d,                  pA  + koff);                              \
        CP16(d + 64 * ROWB,      pA  + koff + a64);                        \
        CP16(d + PL,             pBh + koff);                              \
        CP16(d + PL + 64 * ROWB, pBh + koff + b64);                        \
        CP_COMMIT();                                                       \
    } while (0)

    ISSUE(0);
    ISSUE(1);
    ISSUE(2);

    for (int kt = 0; kt < KT; kt++) {
        // stage kt must be resident: issued groups = min(kt+3, KT), so the
        // allowed outstanding count is min(2, KT-1-kt)  (race-safe tail).
        if (kt < KT - 2)       { CP_WAIT2(); }
        else if (kt == KT - 2) { CP_WAIT1(); }
        else                   { CP_WAIT0(); }
        __syncthreads();     // all warps done with the buffer being rewritten
        if (kt + 3 < KT) ISSUE(kt + 3);
        compute_tile(smb + (kt % NST) * STG, acc, aBase, bBase);
    }
#undef ISSUE

    // ------------------------------ epilogue -------------------------------
    if (MODE == 0 && z == 2) {
        // V: write transposed. Stage tile into SMEM transposed, then
        // coalesced 16B stores along the M dimension of vt_out[H][M].
        __syncthreads();                 // mainloop reads done; reuse smx
        __half* T2 = (__half*)smx;       // [128 h-rows][136 halves (272B)]
#pragma unroll
        for (int mt = 0; mt < 4; mt++)
#pragma unroll
            for (int nt = 0; nt < 4; nt++) {
                const int lr = wm * 64 + mt * 16 + g;
                const int lc = wn * 32 + nt * 8 + tg * 2;
                const float2 b2 = *(const float2*)(bias2 + n0 + lc);
                float* c = acc[mt][nt];
                T2[(lc)     * 136 + lr]     = __float2half_rn(c[0] + b2.x);
                T2[(lc + 1) * 136 + lr]     = __float2half_rn(c[1] + b2.y);
                T2[(lc)     * 136 + lr + 8] = __float2half_rn(c[2] + b2.x);
                T2[(lc + 1) * 136 + lr + 8] = __float2half_rn(c[3] + b2.y);
            }
        __syncthreads();
#pragma unroll
        for (int rep = 0; rep < 8; rep++) {
            const int idx = rep * 256 + tid;
            const int hh = idx >> 4;      // 0..127 (H within tile)
            const int mc = idx & 15;      // 16B chunk along M
            uint4 v = *(const uint4*)((const char*)smx + hh * 272 + mc * 16);
            *(uint4*)(vt_out + (size_t)(n0 + hh) * M_ + m0 + mc * 8) = v;
        }
        return;
    }

#pragma unroll
    for (int mt = 0; mt < 4; mt++) {
        float s0 = 0.f, s1 = 0.f;        // MODE 2 row partial sums
#pragma unroll
        for (int nt = 0; nt < 4; nt++) {
            const int row = m0 + wm * 64 + mt * 16 + g;
            const int col = n0 + wn * 32 + nt * 8 + tg * 2;
            float* c = acc[mt][nt];
            if (MODE == 0) {
                __half* Ch = (__half*)C0 + (size_t)z * sCz;
                const float* bias = (z == 0) ? bias0 : bias1;
                const float2 b2 = *(const float2*)(bias + col);
                *(__half2*)(Ch + (size_t)row * ldc + col) =
                    __floats2half2_rn(c[0] + b2.x, c[1] + b2.y);
                *(__half2*)(Ch + (size_t)(row + 8) * ldc + col) =
                    __floats2half2_rn(c[2] + b2.x, c[3] + b2.y);
            } else if (MODE == 2) {
                __half* Ph = (__half*)C0 + (size_t)z * sCz;
                float e0 = (col     <= row    ) ? exp2f((c[0] * scale - SHIFT) * LOG2E) : 0.f;
                float e1 = (col + 1 <= row    ) ? exp2f((c[1] * scale - SHIFT) * LOG2E) : 0.f;
                float e2 = (col     <= row + 8) ? exp2f((c[2] * scale - SHIFT) * LOG2E) : 0.f;
                float e3 = (col + 1 <= row + 8) ? exp2f((c[3] * scale - SHIFT) * LOG2E) : 0.f;
                s0 += e0 + e1;
                s1 += e2 + e3;
                *(__half2*)(Ph + (size_t)row * ldc + col)       = __floats2half2_rn(e0, e1);
                *(__half2*)(Ph + (size_t)(row + 8) * ldc + col) = __floats2half2_rn(e2, e3);
            } else {
                float* C = (float*)C0 + (size_t)z * sCz;
                const float r0 = 1.f / rsum[z * S_ + row];
                const float r1 = 1.f / rsum[z * S_ + row + 8];
                *(float2*)(C + (size_t)row * ldc + col) =
                    make_float2(c[0] * r0, c[1] * r0);
                *(float2*)(C + (size_t)(row + 8) * ldc + col) =
                    make_float2(c[2] * r1, c[3] * r1);
            }
        }
        if (MODE == 2) {
            // reduce across the quad (tg lanes share the same rows)
            s0 += __shfl_xor_sync(0xffffffffu, s0, 1);
            s0 += __shfl_xor_sync(0xffffffffu, s0, 2);
            s1 += __shfl_xor_sync(0xffffffffu, s1, 1);
            s1 += __shfl_xor_sync(0xffffffffu, s1, 2);
            if (tg == 0) {
                const int row = m0 + wm * 64 + mt * 16 + g;
                atomicAdd(&rsum[z * S_ + row], s0);
                atomicAdd(&rsum[z * S_ + row + 8], s1);
            }
        }
    }
}

// ---------------------------------------------------------------------------
// fp32 -> fp16 conversion (single src)
// ---------------------------------------------------------------------------
__global__ __launch_bounds__(256) void cvt_h(
    const float* __restrict__ in, __half* __restrict__ out)
{
    const size_t i = ((size_t)blockIdx.x * 256 + threadIdx.x) * 4;
    float4 v = *(const float4*)(in + i);
    *(__half2*)(out + i)     = __floats2half2_rn(v.x, v.y);
    *(__half2*)(out + i + 2) = __floats2half2_rn(v.z, v.w);
}

// fp32 -> fp16 conversion for the 3 weight matrices (z-indexed)
__global__ __launch_bounds__(256) void cvt_w(
    const float* __restrict__ w0, const float* __restrict__ w1,
    const float* __restrict__ w2, __half* __restrict__ out)
{
    const int z = blockIdx.y;
    const float* in = (z == 0) ? w0 : ((z == 1) ? w1 : w2);
    const size_t i = ((size_t)blockIdx.x * 256 + threadIdx.x) * 4;
    float4 v = *(const float4*)(in + i);
    __half* o = out + (size_t)z * H_ * D_;
    *(__half2*)(o + i)     = __floats2half2_rn(v.x, v.y);
    *(__half2*)(o + i + 2) = __floats2half2_rn(v.z, v.w);
}

// ---------------------------------------------------------------------------
// Launch pipeline (graph-capturable)
// ---------------------------------------------------------------------------
extern "C" void kernel_launch(void* const* d_in, const int* in_sizes, int n_in,
                              void* d_out, int out_size)
{
    (void)in_sizes; (void)n_in; (void)out_size;
    const float* x  = (const float*)d_in[0];
    const float* Wq = (const float*)d_in[1];
    const float* bq = (const float*)d_in[2];
    const float* Wk = (const float*)d_in[3];
    const float* bk = (const float*)d_in[4];
    const float* Wv = (const float*)d_in[5];
    const float* bv = (const float*)d_in[6];
    float* out = (float*)d_out;

    __half *xh, *wh, *qkv, *vth, *ph;
    float* rsum;
    cudaGetSymbolAddress((void**)&xh,   g_xh);
    cudaGetSymbolAddress((void**)&wh,   g_wh);
    cudaGetSymbolAddress((void**)&qkv,  g_qkv);
    cudaGetSymbolAddress((void**)&vth,  g_vth);
    cudaGetSymbolAddress((void**)&ph,   g_ph);
    cudaGetSymbolAddress((void**)&rsum, g_rsum);

    const __half* qh = qkv;
    const __half* kh = qkv + (size_t)M_ * H_;

    cudaFuncSetAttribute(gemm_h<0>, cudaFuncAttributeMaxDynamicSharedMemorySize, SMEM_BYTES);
    cudaFuncSetAttribute(gemm_h<2>, cudaFuncAttributeMaxDynamicSharedMemorySize, SMEM_BYTES);
    cudaFuncSetAttribute(gemm_h<3>, cudaFuncAttributeMaxDynamicSharedMemorySize, SMEM_BYTES);

    const dim3 blk(256);

    // 0) convert operands to fp16; zero the row-sum accumulator
    cvt_h<<<M_ * D_ / 1024, blk>>>(x, xh);
    cvt_w<<<dim3(H_ * D_ / 1024, 3), blk>>>(Wq, Wk, Wv, wh);
    cudaMemsetAsync(rsum, 0, M_ * sizeof(float));

    // 1) fused QKV projection: z=0/1 -> q/k planes; z=2 -> vth (transposed)
    const dim3 gq(H_ / BN, M_ / BM, 3);  // 3072 CTAs
    gemm_h<0><<<gq, blk, SMEM_BYTES>>>(xh, wh, bq, bk, bv, qkv, vth, nullptr,
                                       D_, D_, D_, H_,
                                       0, (long)H_ * D_, (long)M_ * H_, 1.f);

    // 2) Scores -> p~ = exp(s/32 - SHIFT), fp16, causal; packed triangular
    //    grid; epilogue accumulates row sums into rsum via atomics.
    const dim3 gs(136, 1, B_);  // 1088 CTAs, all live
    gemm_h<2><<<gs, blk, SMEM_BYTES>>>(qh, kh, nullptr, nullptr, nullptr, ph,
                                       nullptr, rsum,
                                       H_, H_, H_, S_,
                                       (long)S_ * H_, (long)S_ * H_, (long)S_ * S_,
                                       0.03125f);

    // 3) O = (p~ @ V) / rsum  (B = V^T, causal k-limit, largest-K tiles first)
    const dim3 gp(H_ / BN, S_ / BM, B_);
    gemm_h<3><<<gp, blk, SMEM_BYTES>>>(ph, vth, nullptr, nullptr, nullptr, out,
                                       nullptr, rsum,
                                       S_, S_, M_, H_,
                                       (long)S_ * S_, (long)S_, (long)S_ * H_, 1.f);
}